// round 4
// baseline (speedup 1.0000x reference)
#include <cuda_runtime.h>
#include <math.h>

#define BB   4
#define NN   8192
#define KK   16
#define INC  3
#define EMB  64
#define HID  128
#define NTOT (BB*NN)        // 32768 nodes
#define ETOT (NTOT*KK)      // 524288 edges

// ---------------- scratch (static device globals; no allocations) ----------------
__device__ float g_emb1[NTOT*EMB];
__device__ float g_emb2[NTOT*EMB];
__device__ int   g_idx [NTOT*KK];
__device__ float g_sq  [NTOT];

// ---------------- squared norms, d=3: sequential mul-then-add (XLA small-row) -------
__global__ __launch_bounds__(256) void sqnorm3_kernel(const float* __restrict__ x,
                                                      float* __restrict__ sq) {
    int i = blockIdx.x * blockDim.x + threadIdx.x;
    if (i < NTOT) {
        float v0 = x[(size_t)i*3+0], v1 = x[(size_t)i*3+1], v2 = x[(size_t)i*3+2];
        float s = __fmul_rn(v0, v0);
        s = __fadd_rn(s, __fmul_rn(v1, v1));
        s = __fadd_rn(s, __fmul_rn(v2, v2));
        sq[i] = s;
    }
}

// ---------------- squared norms, d=64: XLA-GPU warp-tree emulation ------------------
// lane l: partial = x[2l]^2 + x[2l+1]^2 (mul-then-add), then shfl_down tree
// with offsets 16,8,4,2,1 (result taken from lane 0).
__global__ __launch_bounds__(256) void sqnorm64_kernel(const float* __restrict__ x,
                                                       float* __restrict__ sq) {
    int warp = (blockIdx.x * blockDim.x + threadIdx.x) >> 5;
    int l    = threadIdx.x & 31;
    if (warp >= NTOT) return;
    float2 v = reinterpret_cast<const float2*>(x + (size_t)warp*64)[l];
    float p = __fadd_rn(__fmul_rn(v.x, v.x), __fmul_rn(v.y, v.y));
    #pragma unroll
    for (int off = 16; off > 0; off >>= 1)
        p = __fadd_rn(p, __shfl_down_sync(0xffffffffu, p, off));
    if (l == 0) sq[warp] = p;
}

// ---------------- insertion helper: stable top-16 ascending (strict <) --------------
__device__ __forceinline__ void topk_insert(float d, int j, float* bd, int* bi) {
    if (d < bd[KK-1]) {
        float dc = d; int ic = j;
        #pragma unroll
        for (int t = 0; t < KK; ++t) {
            if (dc < bd[t]) {
                float td = bd[t]; bd[t] = dc; dc = td;
                int   ti = bi[t]; bi[t] = ic; ic = ti;
            }
        }
    }
}

// ---------------- kNN, d=3: sequential FMA dot ----------------
__global__ __launch_bounds__(128) void knn3_kernel(const float* __restrict__ x,
                                                   const float* __restrict__ sq,
                                                   int* __restrict__ idxo) {
    const int TILE = 128;
    __shared__ float xs[TILE*3];
    __shared__ float sqs[TILE];
    int g  = blockIdx.y;
    int il = blockIdx.x * 128 + threadIdx.x;
    const float* xg = x + (size_t)g*NN*3;
    float xi0 = xg[il*3+0], xi1 = xg[il*3+1], xi2 = xg[il*3+2];
    float sqi = sq[g*NN + il];

    float bd[KK]; int bi[KK];
    #pragma unroll
    for (int t = 0; t < KK; ++t) { bd[t] = 3.0e38f; bi[t] = 0; }

    for (int jt = 0; jt < NN; jt += TILE) {
        __syncthreads();
        for (int u = threadIdx.x; u < TILE*3; u += 128) xs[u] = xg[jt*3 + u];
        if (threadIdx.x < TILE) sqs[threadIdx.x] = sq[g*NN + jt + threadIdx.x];
        __syncthreads();
        #pragma unroll 4
        for (int jj = 0; jj < TILE; ++jj) {
            int j = jt + jj;
            float acc = 0.f;
            acc = __fmaf_rn(xi0, xs[jj*3+0], acc);
            acc = __fmaf_rn(xi1, xs[jj*3+1], acc);
            acc = __fmaf_rn(xi2, xs[jj*3+2], acc);
            float d = __fsub_rn(__fadd_rn(sqi, sqs[jj]), __fmul_rn(2.0f, acc));
            if (j != il) topk_insert(d, j, bd, bi);
        }
    }
    #pragma unroll
    for (int t = 0; t < KK; ++t) idxo[((size_t)g*NN + il)*KK + t] = bi[t];
}

// ---------------- kNN, d=64: sequential FMA dot, 8-way candidate interleave ---------
__global__ __launch_bounds__(128) void knn64_kernel(const float* __restrict__ x,
                                                    const float* __restrict__ sq,
                                                    int* __restrict__ idxo) {
    const int TILE = 128;
    __shared__ float4 xs[TILE*16];
    __shared__ float  sqs[TILE];
    int g  = blockIdx.y;
    int il = blockIdx.x * 128 + threadIdx.x;
    const float4* xg4 = reinterpret_cast<const float4*>(x + (size_t)g*NN*64);

    float4 xi[16];
    #pragma unroll
    for (int t = 0; t < 16; ++t) xi[t] = xg4[(size_t)il*16 + t];
    float sqi = sq[g*NN + il];

    float bd[KK]; int bi[KK];
    #pragma unroll
    for (int t = 0; t < KK; ++t) { bd[t] = 3.0e38f; bi[t] = 0; }

    for (int jt = 0; jt < NN; jt += TILE) {
        __syncthreads();
        for (int u = threadIdx.x; u < TILE*16; u += 128) xs[u] = xg4[(size_t)jt*16 + u];
        if (threadIdx.x < TILE) sqs[threadIdx.x] = sq[g*NN + jt + threadIdx.x];
        __syncthreads();
        for (int jj = 0; jj < TILE; jj += 8) {
            float acc[8];
            #pragma unroll
            for (int q = 0; q < 8; ++q) acc[q] = 0.f;
            #pragma unroll
            for (int t = 0; t < 16; ++t) {
                float4 u4 = xi[t];
                #pragma unroll
                for (int q = 0; q < 8; ++q) {
                    float4 v = xs[(jj+q)*16 + t];
                    float a = acc[q];
                    a = __fmaf_rn(u4.x, v.x, a);
                    a = __fmaf_rn(u4.y, v.y, a);
                    a = __fmaf_rn(u4.z, v.z, a);
                    a = __fmaf_rn(u4.w, v.w, a);
                    acc[q] = a;
                }
            }
            #pragma unroll
            for (int q = 0; q < 8; ++q) {
                int j = jt + jj + q;
                float d = __fsub_rn(__fadd_rn(sqi, sqs[jj+q]), __fmul_rn(2.0f, acc[q]));
                if (j != il) topk_insert(d, j, bd, bi);
            }
        }
    }
    #pragma unroll
    for (int t = 0; t < KK; ++t) idxo[((size_t)g*NN + il)*KK + t] = bi[t];
}

// ---------------- EdgeConv: sequential-k per (node, neighbor, channel) --------------
// out[i] = max_j ( relu([xi, xj-xi] @ w1 + b1) @ w2 ) + b2   (max commutes with +b2)
template<int D>
__global__ __launch_bounds__(128) void edgeconv_kernel(const float* __restrict__ x,
                                                       const int*   __restrict__ idx,
                                                       const float* __restrict__ w1,
                                                       const float* __restrict__ b1,
                                                       const float* __restrict__ w2,
                                                       const float* __restrict__ b2,
                                                       float* __restrict__ out) {
    extern __shared__ float smem[];
    const int WREG = ((KK*D + KK*64 + D + 3)/4)*4;
    float* sw1 = smem;                 // [2D,64]
    float* sw2 = sw1 + 2*D*64;         // [64,64]
    float* sb1 = sw2 + 4096;
    float* sb2 = sb1 + 64;
    float* wbase = sb2 + 64;
    __shared__ int sidx[4][KK];

    int tid = threadIdx.x, warp = tid >> 5, l = tid & 31;
    for (int u = tid; u < 2*D*64; u += 128) sw1[u] = w1[u];
    for (int u = tid; u < 4096;   u += 128) sw2[u] = w2[u];
    if (tid < 64) { sb1[tid] = b1[tid]; sb2[tid] = b2[tid]; }

    float* sdiff = wbase + warp*WREG;  // [KK,D]
    float* sh1   = sdiff + KK*D;       // [KK,64]
    float* sxi   = sh1 + KK*64;        // [D]

    int n = blockIdx.x*4 + warp;       // global node
    int g = n / NN, il = n % NN;
    const float* xg = x + (size_t)g*NN*D;
    if (l < KK) sidx[warp][l] = idx[(size_t)n*KK + l];
    for (int t = l; t < D; t += 32) sxi[t] = xg[(size_t)il*D + t];
    __syncthreads();

    for (int u = l; u < KK*D; u += 32) {
        int j = u / D, t = u - j*D;
        sdiff[u] = __fsub_rn(xg[(size_t)sidx[warp][j]*D + t], sxi[t]);
    }
    __syncwarp();

    // layer-1 xi prefix (t = 0..D-1), sequential FMA from 0
    float baseA = 0.f, baseC = 0.f;
    for (int t = 0; t < D; ++t) {
        float f = sxi[t];
        baseA = __fmaf_rn(f, sw1[t*64 + l],      baseA);
        baseC = __fmaf_rn(f, sw1[t*64 + l + 32], baseC);
    }

    // layer-1 diff part (t = D..2D-1), sequential continuation, j-blocked by 8
    #pragma unroll
    for (int jb = 0; jb < 2; ++jb) {
        float aA[8], aC[8];
        #pragma unroll
        for (int q = 0; q < 8; ++q) { aA[q] = baseA; aC[q] = baseC; }

        if (D % 4 == 0) {
            for (int t = 0; t < D; t += 4) {
                float wa0 = sw1[(D+t+0)*64+l],    wa1 = sw1[(D+t+1)*64+l];
                float wa2 = sw1[(D+t+2)*64+l],    wa3 = sw1[(D+t+3)*64+l];
                float wc0 = sw1[(D+t+0)*64+l+32], wc1 = sw1[(D+t+1)*64+l+32];
                float wc2 = sw1[(D+t+2)*64+l+32], wc3 = sw1[(D+t+3)*64+l+32];
                #pragma unroll
                for (int q = 0; q < 8; ++q) {
                    float4 f = *reinterpret_cast<const float4*>(&sdiff[(jb*8+q)*D + t]);
                    float a = aA[q], c = aC[q];
                    a = __fmaf_rn(f.x, wa0, a); a = __fmaf_rn(f.y, wa1, a);
                    a = __fmaf_rn(f.z, wa2, a); a = __fmaf_rn(f.w, wa3, a);
                    c = __fmaf_rn(f.x, wc0, c); c = __fmaf_rn(f.y, wc1, c);
                    c = __fmaf_rn(f.z, wc2, c); c = __fmaf_rn(f.w, wc3, c);
                    aA[q] = a; aC[q] = c;
                }
            }
        } else {
            for (int t = 0; t < D; ++t) {
                float wa = sw1[(D+t)*64+l], wc = sw1[(D+t)*64+l+32];
                #pragma unroll
                for (int q = 0; q < 8; ++q) {
                    float f = sdiff[(jb*8+q)*D + t];
                    aA[q] = __fmaf_rn(f, wa, aA[q]);
                    aC[q] = __fmaf_rn(f, wc, aC[q]);
                }
            }
        }
        #pragma unroll
        for (int q = 0; q < 8; ++q) {
            int j = jb*8 + q;
            sh1[j*64 + l]      = fmaxf(__fadd_rn(aA[q], sb1[l]),    0.f);
            sh1[j*64 + l + 32] = fmaxf(__fadd_rn(aC[q], sb1[l+32]), 0.f);
        }
    }
    __syncwarp();

    // layer-2: sequential over k=0..63 per neighbor, then exact max, then +b2
    float mA = -3.0e38f, mC = -3.0e38f;
    #pragma unroll
    for (int jb = 0; jb < 2; ++jb) {
        float aA[8], aC[8];
        #pragma unroll
        for (int q = 0; q < 8; ++q) { aA[q] = 0.f; aC[q] = 0.f; }
        for (int k = 0; k < 64; k += 4) {
            float wa0 = sw2[(k+0)*64+l],    wa1 = sw2[(k+1)*64+l];
            float wa2 = sw2[(k+2)*64+l],    wa3 = sw2[(k+3)*64+l];
            float wc0 = sw2[(k+0)*64+l+32], wc1 = sw2[(k+1)*64+l+32];
            float wc2 = sw2[(k+2)*64+l+32], wc3 = sw2[(k+3)*64+l+32];
            #pragma unroll
            for (int q = 0; q < 8; ++q) {
                float4 h = *reinterpret_cast<const float4*>(&sh1[(jb*8+q)*64 + k]);
                float a = aA[q], c = aC[q];
                a = __fmaf_rn(h.x, wa0, a); a = __fmaf_rn(h.y, wa1, a);
                a = __fmaf_rn(h.z, wa2, a); a = __fmaf_rn(h.w, wa3, a);
                c = __fmaf_rn(h.x, wc0, c); c = __fmaf_rn(h.y, wc1, c);
                c = __fmaf_rn(h.z, wc2, c); c = __fmaf_rn(h.w, wc3, c);
                aA[q] = a; aC[q] = c;
            }
        }
        #pragma unroll
        for (int q = 0; q < 8; ++q) { mA = fmaxf(mA, aA[q]); mC = fmaxf(mC, aC[q]); }
    }
    out[(size_t)n*64 + l]      = __fadd_rn(mA, sb2[l]);
    out[(size_t)n*64 + l + 32] = __fadd_rn(mC, sb2[l+32]);
}

// ---------------- final per-edge MLP + edge_index emit ----------------
__global__ __launch_bounds__(128) void mlp_kernel(const float* __restrict__ emb,
                                                  const int*   __restrict__ idx,
                                                  const float* __restrict__ w1,
                                                  const float* __restrict__ b1,
                                                  const float* __restrict__ w2,
                                                  const float* __restrict__ b2,
                                                  float* __restrict__ out, int out_size) {
    extern __shared__ float smem[];
    const int WREG = KK*64 + 64;      // 1088 floats per warp
    float* sw1 = smem;                // [128,128]
    float* sb1 = sw1 + 16384;
    float* sw2 = sb1 + 128;
    float* wbase = sw2 + 128;
    __shared__ int sidx[4][KK];

    int tid = threadIdx.x, warp = tid >> 5, l = tid & 31;
    for (int u = tid; u < 16384; u += 128) sw1[u] = w1[u];
    if (tid < 128) { sb1[tid] = b1[tid]; sw2[tid] = w2[tid]; }

    float* ssf = wbase + warp*WREG;   // [KK,64] src feats
    float* sdf = ssf + KK*64;         // [64] dst feat

    int n = blockIdx.x*4 + warp;
    int g = n / NN;
    if (l < KK) sidx[warp][l] = idx[(size_t)n*KK + l];
    sdf[l]      = emb[(size_t)n*64 + l];
    sdf[l + 32] = emb[(size_t)n*64 + l + 32];
    __syncthreads();

    for (int u = l; u < KK*64; u += 32) {
        int j = u >> 6, t = u & 63;
        ssf[u] = emb[((size_t)g*NN + sidx[warp][j])*64 + t];
    }
    __syncwarp();

    // dst-common hidden contribution (w1 rows 64..127) + b1
    float db[4];
    #pragma unroll
    for (int q = 0; q < 4; ++q) db[q] = sb1[l + 32*q];
    for (int t = 0; t < 64; ++t) {
        float f = sdf[t];
        #pragma unroll
        for (int q = 0; q < 4; ++q) db[q] = __fmaf_rn(f, sw1[(64+t)*128 + l + 32*q], db[q]);
    }

    // per-neighbor src contribution (w1 rows 0..63)
    float acc[KK][4];
    #pragma unroll
    for (int j = 0; j < KK; ++j)
        #pragma unroll
        for (int q = 0; q < 4; ++q) acc[j][q] = 0.f;

    for (int t = 0; t < 64; t += 4) {
        float wv[4][4];
        #pragma unroll
        for (int dt = 0; dt < 4; ++dt)
            #pragma unroll
            for (int q = 0; q < 4; ++q) wv[dt][q] = sw1[(t+dt)*128 + l + 32*q];
        #pragma unroll
        for (int j = 0; j < KK; ++j) {
            float4 f = *reinterpret_cast<const float4*>(&ssf[j*64 + t]);
            #pragma unroll
            for (int q = 0; q < 4; ++q) {
                float a = acc[j][q];
                a = __fmaf_rn(f.x, wv[0][q], a);
                a = __fmaf_rn(f.y, wv[1][q], a);
                a = __fmaf_rn(f.z, wv[2][q], a);
                a = __fmaf_rn(f.w, wv[3][q], a);
                acc[j][q] = a;
            }
        }
    }

    float w2v[4];
    #pragma unroll
    for (int q = 0; q < 4; ++q) w2v[q] = sw2[l + 32*q];
    float b2s = b2[0];

    float myp = 0.f;
    #pragma unroll
    for (int j = 0; j < KK; ++j) {
        float p = 0.f;
        #pragma unroll
        for (int q = 0; q < 4; ++q) p += fmaxf(acc[j][q] + db[q], 0.f) * w2v[q];
        #pragma unroll
        for (int off = 16; off > 0; off >>= 1) p += __shfl_xor_sync(0xffffffffu, p, off);
        if (l == j) myp = p;
    }
    if (l < KK) {
        int e = n*KK + l;
        float z = myp + b2s;
        out[e] = 1.0f / (1.0f + expf(-z));
        if (out_size >= 3*ETOT) {
            out[ETOT   + e] = (float)(g*NN + sidx[warp][l]);
            out[2*ETOT + e] = (float)n;
        }
    }
}

// ---------------- launch ----------------
extern "C" void kernel_launch(void* const* d_in, const int* in_sizes, int n_in,
                              void* d_out, int out_size) {
    const float* x      = (const float*)d_in[0];
    // d_in[1] = batch (int64), unused (equal-sized graphs)
    const float* c1_w1  = (const float*)d_in[2];
    const float* c1_b1  = (const float*)d_in[3];
    const float* c1_w2  = (const float*)d_in[4];
    const float* c1_b2  = (const float*)d_in[5];
    const float* c2_w1  = (const float*)d_in[6];
    const float* c2_b1  = (const float*)d_in[7];
    const float* c2_w2  = (const float*)d_in[8];
    const float* c2_b2  = (const float*)d_in[9];
    const float* mlp_w1 = (const float*)d_in[10];
    const float* mlp_b1 = (const float*)d_in[11];
    const float* mlp_w2 = (const float*)d_in[12];
    const float* mlp_b2 = (const float*)d_in[13];
    float* out = (float*)d_out;

    float *emb1, *emb2, *sq; int *idx;
    cudaGetSymbolAddress((void**)&emb1, g_emb1);
    cudaGetSymbolAddress((void**)&emb2, g_emb2);
    cudaGetSymbolAddress((void**)&sq,   g_sq);
    cudaGetSymbolAddress((void**)&idx,  g_idx);

    const int WREG64 = ((KK*64 + KK*64 + 64 + 3)/4)*4;               // 2112
    const int WREG3  = ((KK*3  + KK*64 + 3  + 3)/4)*4;               // 1076
    size_t sm_ec64 = (size_t)(2*64*64 + 4096 + 128 + 4*WREG64) * 4;
    size_t sm_ec3  = (size_t)(2*3*64  + 4096 + 128 + 4*WREG3 ) * 4;
    size_t sm_mlp  = (size_t)(16384 + 128 + 128 + 4*(KK*64+64)) * 4;

    cudaFuncSetAttribute(edgeconv_kernel<64>, cudaFuncAttributeMaxDynamicSharedMemorySize, (int)sm_ec64);
    cudaFuncSetAttribute(edgeconv_kernel<3>,  cudaFuncAttributeMaxDynamicSharedMemorySize, (int)sm_ec3);
    cudaFuncSetAttribute(mlp_kernel,          cudaFuncAttributeMaxDynamicSharedMemorySize, (int)sm_mlp);

    dim3 knn_grid(NN/128, BB);

    // stage 1: kNN on raw x (d=3) -> EdgeConv1 -> emb1
    sqnorm3_kernel<<<NTOT/256, 256>>>(x, sq);
    knn3_kernel<<<knn_grid, 128>>>(x, sq, idx);
    edgeconv_kernel<3><<<NTOT/4, 128, sm_ec3>>>(x, idx, c1_w1, c1_b1, c1_w2, c1_b2, emb1);

    // stage 2: kNN on emb1 (d=64) -> EdgeConv2 -> emb2
    sqnorm64_kernel<<<(NTOT*32)/256, 256>>>(emb1, sq);
    knn64_kernel<<<knn_grid, 128>>>(emb1, sq, idx);
    edgeconv_kernel<64><<<NTOT/4, 128, sm_ec64>>>(emb1, idx, c2_w1, c2_b1, c2_w2, c2_b2, emb2);

    // stage 3: final kNN graph on emb2 -> per-edge MLP + edge_index
    sqnorm64_kernel<<<(NTOT*32)/256, 256>>>(emb2, sq);
    knn64_kernel<<<knn_grid, 128>>>(emb2, sq, idx);
    mlp_kernel<<<NTOT/4, 128, sm_mlp>>>(emb2, idx, mlp_w1, mlp_b1, mlp_w2, mlp_b2, out, out_size);
}